// round 12
// baseline (speedup 1.0000x reference)
#include <cuda_runtime.h>
#include <cuda_fp16.h>
#include <cstdint>

// TM-CFAR: out = rd_map / trimmed_mean(sorted 126 reference cells, ranks [31,94))
// Window 9x15, guard 3x3, zero padding.
//
// Round-12: warp per 4 pixels; SHARED-WINDOW histogram.
//  - full 9x15 window-union histogram: 162 cells, ONE atomic per cell, value =
//    byte-mask of which quad pixels' windows contain that column
//  - separate 3x3 guard-union histogram (18 cells), subtracted byte-wise
//    during the cumulative load (guard <= full per byte: borrow-free)
//  - scan / byte-SIMD bucket search / epilogue unchanged from round 11
//  - clean quads: 256-wide bucket direct (midpoint +-128); padding-affected
//    quads: 8 exact bisection steps inside bucket

#define TILE_WQ   50      // qword tile stride (u64 units)
#define PAIR_W    48      // transient pair-tile stride (u32 units)
#define TILE_ROWS 16
#define KBIAS     1024
#define KSCALE    30720.0f
#define SENT2     0x7BFF7BFFu   // max-finite fp16: never below any threshold, hmul-safe

static __device__ __forceinline__ unsigned h2u(__half2 h) { return *reinterpret_cast<unsigned*>(&h); }
static __device__ __forceinline__ __half2  u2h(unsigned u) { return *reinterpret_cast<__half2*>(&u); }

// STARTBIT < STOPBIT => zero bisection steps, epilogue only, MIDOFF = 1<<(STOPBIT-1)
template <int STARTBIT, int STOPBIT>
static __device__ __forceinline__ void bisect_pair(
    unsigned pk0, unsigned pk1, unsigned pk2, unsigned pk3,
    unsigned A2, unsigned B2,
    float& scP, float& scQ)
{
    const __half2 magic = u2h(0x64006400u);   // (1024.0, 1024.0)

    #pragma unroll
    for (int bit = STARTBIT; bit >= STOPBIT; --bit) {
        const unsigned step2 = (1u << bit) * 0x10001u;
        const __half2 mA = u2h(A2 + step2);
        const __half2 mB = u2h(B2 + step2);

        __half2 sA = __hadd2(__hadd2(__hlt2(u2h(pk0), mA), __hlt2(u2h(pk1), mA)),
                             __hadd2(__hlt2(u2h(pk2), mA), __hlt2(u2h(pk3), mA)));
        __half2 sB = __hadd2(__hadd2(__hlt2(u2h(pk0), mB), __hlt2(u2h(pk1), mB)),
                             __hadd2(__hlt2(u2h(pk2), mB), __hlt2(u2h(pk3), mB)));
        const unsigned Ar = h2u(__hadd2(sA, magic));   // bytes (cAP, 0x64, cAQ, 0x64)
        const unsigned Br = h2u(__hadd2(sB, magic));
        unsigned cc = __byte_perm(Ar, Br, 0x6420);     // (cAP, cAQ, cBP, cBQ)
        cc = __reduce_add_sync(0xffffffffu, cc);

        // byte-wise accept flags: bytes 0,1 vs 30 ; bytes 2,3 vs 94
        const unsigned f = ((0xDEDE9E9Eu - cc) >> 7) & 0x01010101u;
        A2 += __byte_perm(f, 0, 0x4140) << bit;   // (fAP | fAQ<<16) << bit
        B2 += __byte_perm(f, 0, 0x4342) << bit;
    }

    const int MIDOFF = (STOPBIT > 0) ? (1 << (STOPBIT - 1)) : 0;

    // ---- epilogue: exact counts below brackets + masked range sums ----
    const __half2 hA = u2h(A2), hB = u2h(B2);
    const __half2 lA0 = __hlt2(u2h(pk0), hA), lA1 = __hlt2(u2h(pk1), hA);
    const __half2 lA2v = __hlt2(u2h(pk2), hA), lA3 = __hlt2(u2h(pk3), hA);
    const __half2 lB0 = __hlt2(u2h(pk0), hB), lB1 = __hlt2(u2h(pk1), hB);
    const __half2 lB2v = __hlt2(u2h(pk2), hB), lB3 = __hlt2(u2h(pk3), hB);

    const unsigned in0 = h2u(lB0) & ~h2u(lA0);
    const unsigned in1 = h2u(lB1) & ~h2u(lA1);
    const unsigned in2 = h2u(lB2v) & ~h2u(lA2v);
    const unsigned in3 = h2u(lB3) & ~h2u(lA3);

    const unsigned km0 = h2u(__hmul2(u2h(pk0), u2h(in0)));
    const unsigned km1 = h2u(__hmul2(u2h(pk1), u2h(in1)));
    const unsigned km2 = h2u(__hmul2(u2h(pk2), u2h(in2)));
    const unsigned km3 = h2u(__hmul2(u2h(pk3), u2h(in3)));

    // halfword-pair pack + SIMD add (lanes <= 2*31743, no carry)
    const unsigned lo01 = __byte_perm(km0, km1, 0x5410);
    const unsigned lo23 = __byte_perm(km2, km3, 0x5410);
    const unsigned hi01 = __byte_perm(km0, km1, 0x7632);
    const unsigned hi23 = __byte_perm(km2, km3, 0x7632);
    const unsigned vlo = __vadd2(lo01, lo23);
    const unsigned vhi = __vadd2(hi01, hi23);
    unsigned sP = (vlo & 0xFFFFu) + (vlo >> 16);
    unsigned sQ = (vhi & 0xFFFFu) + (vhi >> 16);

    const __half2 cA2 = __hadd2(__hadd2(lA0, lA1), __hadd2(lA2v, lA3));
    const __half2 cB2 = __hadd2(__hadd2(lB0, lB1), __hadd2(lB2v, lB3));
    unsigned ccf = __byte_perm(h2u(__hadd2(cA2, magic)), h2u(__hadd2(cB2, magic)), 0x6420);

    ccf = __reduce_add_sync(0xffffffffu, ccf);
    sP  = __reduce_add_sync(0xffffffffu, sP);
    sQ  = __reduce_add_sync(0xffffffffu, sQ);

    const int cAP = (int)(ccf & 255u);
    const int cAQ = (int)((ccf >> 8) & 255u);
    const int cBP = (int)((ccf >> 16) & 255u);
    const int cBQ = (int)(ccf >> 24);

    const int TAP = (int)(A2 & 0xFFFFu) + MIDOFF, TAQ = (int)(A2 >> 16) + MIDOFF;
    const int TBP = (int)(B2 & 0xFFFFu) + MIDOFF, TBQ = (int)(B2 >> 16) + MIDOFF;

    const int keptP = (int)sP - KBIAS * (cBP - cAP)
                    + (94 - cBP) * (TBP - KBIAS) - (31 - cAP) * (TAP - KBIAS);
    const int keptQ = (int)sQ - KBIAS * (cBQ - cAQ)
                    + (94 - cBQ) * (TBQ - KBIAS) - (31 - cAQ) * (TAQ - KBIAS);

    scP = __fdividef(63.0f * KSCALE, (float)keptP);
    scQ = __fdividef(63.0f * KSCALE, (float)keptQ);
}

__global__ __launch_bounds__(256, 4)
void tmcfar_kernel(const float* __restrict__ in, float* __restrict__ out,
                   int H, int W)
{
    __shared__ unsigned pairs[TILE_ROWS * PAIR_W];            // 3072 B (build only)
    __shared__ unsigned long long qtile[TILE_ROWS * TILE_WQ]; // 6400 B
    __shared__ int      offs[128];                            // qword-unit offsets
    __shared__ __align__(16) unsigned hfull[8][128];          // byte p = pixel p count
    __shared__ __align__(16) unsigned hguard[8][128];

    const int tid  = threadIdx.x;
    const int lane = tid & 31;
    const int wrp  = tid >> 5;
    const int bz   = blockIdx.z;
    const int py0  = blockIdx.y * 8;
    const int px0  = blockIdx.x * 32;

    // compacted (dy,dx) offsets of the 126 reference cells (qword units)
    if (tid < 135) {
        int r = tid / 15, c = tid - r * 15;
        bool guard = (r >= 3 && r <= 5 && c >= 6 && c <= 8);
        if (!guard) {
            int rowsBefore = min(max(r - 3, 0), 3);
            int sameRow    = (r >= 3 && r <= 5) ? min(max(c - 6, 0), 3) : 0;
            int gb = 3 * rowsBefore + sameRow;
            offs[tid - gb] = (r - 4) * TILE_WQ + (c - 7);
        }
    }

    // ---- phase 1: pair tile, entry c = key[c] | key[c+1]<<16 (all 48 cols defined) ----
    const int gy0 = py0 - 4, gx0 = px0 - 7;
    const float* inb = in + (size_t)bz * H * W;
    for (int idx = tid; idx < TILE_ROWS * PAIR_W; idx += 256) {
        int r = idx / PAIR_W, c = idx - r * PAIR_W;
        int gy = gy0 + r, gx = gx0 + c;
        bool okr = (gy >= 0 && gy < H);
        float v0 = (okr && gx >= 0     && gx < W)     ? inb[gy * W + gx]     : 0.0f;
        float v1 = (okr && gx + 1 >= 0 && gx + 1 < W) ? inb[gy * W + gx + 1] : 0.0f;
        unsigned k0 = min((unsigned)(v0 * KSCALE), 30719u) + (unsigned)KBIAS;
        unsigned k1 = min((unsigned)(v1 * KSCALE), 30719u) + (unsigned)KBIAS;
        pairs[r * PAIR_W + c] = k0 | (k1 << 16);
    }
    __syncthreads();

    // ---- phase 2: qword tile, entry c = k[c..c+3] (c in 0..45) ----
    for (int idx = tid; idx < TILE_ROWS * 46; idx += 256) {
        int r = idx / 46, c = idx - r * 46;
        qtile[r * TILE_WQ + c] =
            (unsigned long long)pairs[r * PAIR_W + c]
          | ((unsigned long long)pairs[r * PAIR_W + c + 2] << 32);
    }
    __syncthreads();

    const int py = py0 + wrp;
    const float centerf = inb[py * W + px0 + lane];
    const bool exY = (py < 4) | (py >= H - 4);   // warp-uniform

    const int o0 = offs[lane];
    const int o1 = offs[lane + 32];
    const int o2 = offs[lane + 64];
    const int o3 = (lane < 30) ? offs[lane + 96] : 0;
    const bool has3 = (lane < 30);

    // ---- per-lane window-histogram slots (fixed across quads; +16 u16/quad) ----
    // full union: 9 rows x 18 cols = 162 cells; n = lane + 32*j
    int fIdx[6]; unsigned fMask[6];
    #pragma unroll
    for (int j = 0; j < 6; ++j) {
        int n = lane + 32 * j;
        if (n < 162) {
            int r = n / 18, u = n - r * 18;
            fIdx[j] = ((wrp + r) * TILE_WQ + u) * 4;   // u16 index of k[u] in row wrp+r
            unsigned m = 0;
            if (u <= 14)            m |= 0x01u;        // P: window cols u in [0,14]
            if (u >= 1 && u <= 15)  m |= 0x100u;       // Q
            if (u >= 2 && u <= 16)  m |= 0x10000u;     // R
            if (u >= 3)             m |= 0x1000000u;   // S (u<=17 always)
            fMask[j] = m;
        } else { fIdx[j] = 0; fMask[j] = 0; }
    }
    // guard union: 3 rows x 6 cols = 18 cells; lanes 0..17
    int gIdxv = 0; unsigned gMaskv = 0;
    if (lane < 18) {
        int r3 = lane / 6, v = lane - r3 * 6;
        gIdxv = ((wrp + 3 + r3) * TILE_WQ + (6 + v)) * 4;
        unsigned m = 0;
        if (v <= 2)            m |= 0x01u;             // P guard cols v in [0,2]
        if (v >= 1 && v <= 3)  m |= 0x100u;
        if (v >= 2 && v <= 4)  m |= 0x10000u;
        if (v >= 3)            m |= 0x1000000u;        // v<=5 always
        gMaskv = m;
    }

    const unsigned short* qs = (const unsigned short*)qtile;
    const unsigned long long* qrow = &qtile[(wrp + 4) * TILE_WQ + 7];
    unsigned* hf = &hfull[wrp][0];
    unsigned* hg = &hguard[wrp][0];
    float myscale = 0.0f;

    #pragma unroll 1
    for (int i = 0; i < 8; ++i) {
        // ---- epilogue gather keys: one LDS.64 per reference cell ----
        const unsigned long long* p = qrow + 4 * i;
        const unsigned long long w0 = p[o0];
        const unsigned long long w1 = p[o1];
        const unsigned long long w2 = p[o2];
        const unsigned long long w3 = p[o3];
        const unsigned a0 = (unsigned)w0, b0 = (unsigned)(w0 >> 32);
        const unsigned a1 = (unsigned)w1, b1 = (unsigned)(w1 >> 32);
        const unsigned a2 = (unsigned)w2, b2 = (unsigned)(w2 >> 32);
        const unsigned a3 = has3 ? (unsigned)w3 : SENT2;
        const unsigned b3 = has3 ? (unsigned)(w3 >> 32) : SENT2;

        // ---- shared-window histograms: 7 atomics total per lane ----
        *reinterpret_cast<uint4*>(&hf[lane * 4]) = make_uint4(0u, 0u, 0u, 0u);
        *reinterpret_cast<uint4*>(&hg[lane * 4]) = make_uint4(0u, 0u, 0u, 0u);
        __syncwarp();
        const int sh = 16 * i;   // window slides 4 cols/quad = 16 u16
        #pragma unroll
        for (int j = 0; j < 5; ++j) {
            const unsigned k = qs[fIdx[j] + sh];
            atomicAdd(&hf[k >> 8], fMask[j]);
        }
        if (lane < 2) {
            const unsigned k = qs[fIdx[5] + sh];
            atomicAdd(&hf[k >> 8], fMask[5]);
        }
        if (lane < 18) {
            const unsigned k = qs[gIdxv + sh];
            atomicAdd(&hg[k >> 8], gMaskv);
        }
        __syncwarp();

        // ---- cum load: net = full - guard (byte-safe: guard <= full per byte) ----
        const uint4 cf = *reinterpret_cast<const uint4*>(&hf[lane * 4]);
        const uint4 cg = *reinterpret_cast<const uint4*>(&hg[lane * 4]);
        unsigned q0 = cf.x - cg.x;
        unsigned q1 = q0 + (cf.y - cg.y);
        unsigned q2 = q1 + (cf.z - cg.z);
        unsigned q3 = q2 + (cf.w - cg.w);
        unsigned incl = q3;
        #pragma unroll
        for (int d = 1; d < 32; d <<= 1) {
            unsigned t = __shfl_up_sync(0xffffffffu, incl, d);
            if (lane >= d) incl += t;
        }
        const unsigned excl = incl - q3;
        q0 += excl; q1 += excl; q2 += excl; q3 += excl;

        // ---- byte-SIMD bucket search for all 4 pixels, TWO REDUX total ----
        const unsigned g30 = (((0x9E9E9E9Eu - q0) >> 7) & 0x01010101u)
                           + (((0x9E9E9E9Eu - q1) >> 7) & 0x01010101u)
                           + (((0x9E9E9E9Eu - q2) >> 7) & 0x01010101u)
                           + (((0x9E9E9E9Eu - q3) >> 7) & 0x01010101u);
        const unsigned g94 = (((0xDEDEDEDEu - q0) >> 7) & 0x01010101u)
                           + (((0xDEDEDEDEu - q1) >> 7) & 0x01010101u)
                           + (((0xDEDEDEDEu - q2) >> 7) & 0x01010101u)
                           + (((0xDEDEDEDEu - q3) >> 7) & 0x01010101u);
        const unsigned w30 = __reduce_add_sync(0xffffffffu, g30);  // bytes (bAP,bAQ,bAR,bAS)
        const unsigned w94 = __reduce_add_sync(0xffffffffu, g94);  // bytes (bBP,bBQ,bBR,bBS)

        // bucket base = bin<<8: bytes to halfword-high positions per pair
        const unsigned A2pq = __byte_perm(w30, 0, 0x1404);   // (0,bAP,0,bAQ)
        const unsigned B2pq = __byte_perm(w94, 0, 0x1404);
        const unsigned A2rs = __byte_perm(w30, 0, 0x3424);   // (0,bAR,0,bAS)
        const unsigned B2rs = __byte_perm(w94, 0, 0x3424);

        float s0, s1, s2, s3;
        const int pxP = px0 + 4 * i;
        if (exY | (pxP < 7) | (pxP + 3 >= W - 7)) {
            // window touches zero padding: 8 exact bisection steps inside bucket
            bisect_pair<7, 0>(a0, a1, a2, a3, A2pq, B2pq, s0, s1);
            bisect_pair<7, 0>(b0, b1, b2, b3, A2rs, B2rs, s2, s3);
        } else {
            // clean: 256-wide bucket direct, midpoint +-128 substitution
            bisect_pair<7, 8>(a0, a1, a2, a3, A2pq, B2pq, s0, s1);
            bisect_pair<7, 8>(b0, b1, b2, b3, A2rs, B2rs, s2, s3);
        }
        if (lane == 4 * i)     myscale = s0;
        if (lane == 4 * i + 1) myscale = s1;
        if (lane == 4 * i + 2) myscale = s2;
        if (lane == 4 * i + 3) myscale = s3;
    }

    out[(size_t)bz * H * W + py * W + px0 + lane] = centerf * myscale;
}

extern "C" void kernel_launch(void* const* d_in, const int* in_sizes, int n_in,
                              void* d_out, int out_size)
{
    const float* in = (const float*)d_in[0];
    float* out = (float*)d_out;
    const int H = 512, W = 512;
    const int B = in_sizes[0] / (H * W);

    dim3 grid(W / 32, H / 8, B);
    dim3 block(256);
    tmcfar_kernel<<<grid, block>>>(in, out, H, W);
}

// round 14
// speedup vs baseline: 1.0590x; 1.0590x over previous
#include <cuda_runtime.h>
#include <cuda_fp16.h>
#include <cstdint>

// TM-CFAR: out = rd_map / trimmed_mean(sorted 126 reference cells, ranks [31,94))
// Window 9x15, guard 3x3, zero padding.
//
// Round-13R (resubmit; prior attempt hit a container-infra failure):
// warp per 4 pixels; single shared-window histogram with guard-folded net
// masks, slot table in shared memory (register relief).
//  - full 9x15 window-union: 162 cells, ONE atomic per cell, value = byte-mask
//    of which quad pixels count that cell (guard cells pre-subtracted in mask)
//  - slot table: u64 {mask32, idx16} x 192 in smem, warp-invariant
//  - scan / byte-SIMD bucket search / epilogue unchanged (bit-identical)
//  - clean quads: 256-wide bucket direct (midpoint +-128); padding-affected
//    quads: 8 exact bisection steps inside bucket

#define TILE_WQ   50      // qword tile stride (u64 units)
#define PAIR_W    48      // transient pair-tile stride (u32 units)
#define TILE_ROWS 16
#define KBIAS     1024
#define KSCALE    30720.0f
#define SENT2     0x7BFF7BFFu   // max-finite fp16: never below any threshold, hmul-safe

static __device__ __forceinline__ unsigned h2u(__half2 h) { return *reinterpret_cast<unsigned*>(&h); }
static __device__ __forceinline__ __half2  u2h(unsigned u) { return *reinterpret_cast<__half2*>(&u); }

// STARTBIT < STOPBIT => zero bisection steps, epilogue only, MIDOFF = 1<<(STOPBIT-1)
template <int STARTBIT, int STOPBIT>
static __device__ __forceinline__ void bisect_pair(
    unsigned pk0, unsigned pk1, unsigned pk2, unsigned pk3,
    unsigned A2, unsigned B2,
    float& scP, float& scQ)
{
    const __half2 magic = u2h(0x64006400u);   // (1024.0, 1024.0)

    #pragma unroll
    for (int bit = STARTBIT; bit >= STOPBIT; --bit) {
        const unsigned step2 = (1u << bit) * 0x10001u;
        const __half2 mA = u2h(A2 + step2);
        const __half2 mB = u2h(B2 + step2);

        __half2 sA = __hadd2(__hadd2(__hlt2(u2h(pk0), mA), __hlt2(u2h(pk1), mA)),
                             __hadd2(__hlt2(u2h(pk2), mA), __hlt2(u2h(pk3), mA)));
        __half2 sB = __hadd2(__hadd2(__hlt2(u2h(pk0), mB), __hlt2(u2h(pk1), mB)),
                             __hadd2(__hlt2(u2h(pk2), mB), __hlt2(u2h(pk3), mB)));
        const unsigned Ar = h2u(__hadd2(sA, magic));   // bytes (cAP, 0x64, cAQ, 0x64)
        const unsigned Br = h2u(__hadd2(sB, magic));
        unsigned cc = __byte_perm(Ar, Br, 0x6420);     // (cAP, cAQ, cBP, cBQ)
        cc = __reduce_add_sync(0xffffffffu, cc);

        // byte-wise accept flags: bytes 0,1 vs 30 ; bytes 2,3 vs 94
        const unsigned f = ((0xDEDE9E9Eu - cc) >> 7) & 0x01010101u;
        A2 += __byte_perm(f, 0, 0x4140) << bit;   // (fAP | fAQ<<16) << bit
        B2 += __byte_perm(f, 0, 0x4342) << bit;
    }

    const int MIDOFF = (STOPBIT > 0) ? (1 << (STOPBIT - 1)) : 0;

    // ---- epilogue: exact counts below brackets + masked range sums ----
    const __half2 hA = u2h(A2), hB = u2h(B2);
    const __half2 lA0 = __hlt2(u2h(pk0), hA), lA1 = __hlt2(u2h(pk1), hA);
    const __half2 lA2v = __hlt2(u2h(pk2), hA), lA3 = __hlt2(u2h(pk3), hA);
    const __half2 lB0 = __hlt2(u2h(pk0), hB), lB1 = __hlt2(u2h(pk1), hB);
    const __half2 lB2v = __hlt2(u2h(pk2), hB), lB3 = __hlt2(u2h(pk3), hB);

    const unsigned in0 = h2u(lB0) & ~h2u(lA0);
    const unsigned in1 = h2u(lB1) & ~h2u(lA1);
    const unsigned in2 = h2u(lB2v) & ~h2u(lA2v);
    const unsigned in3 = h2u(lB3) & ~h2u(lA3);

    const unsigned km0 = h2u(__hmul2(u2h(pk0), u2h(in0)));
    const unsigned km1 = h2u(__hmul2(u2h(pk1), u2h(in1)));
    const unsigned km2 = h2u(__hmul2(u2h(pk2), u2h(in2)));
    const unsigned km3 = h2u(__hmul2(u2h(pk3), u2h(in3)));

    // halfword-pair pack + SIMD add (lanes <= 2*31743, no carry)
    const unsigned lo01 = __byte_perm(km0, km1, 0x5410);
    const unsigned lo23 = __byte_perm(km2, km3, 0x5410);
    const unsigned hi01 = __byte_perm(km0, km1, 0x7632);
    const unsigned hi23 = __byte_perm(km2, km3, 0x7632);
    const unsigned vlo = __vadd2(lo01, lo23);
    const unsigned vhi = __vadd2(hi01, hi23);
    unsigned sP = (vlo & 0xFFFFu) + (vlo >> 16);
    unsigned sQ = (vhi & 0xFFFFu) + (vhi >> 16);

    const __half2 cA2 = __hadd2(__hadd2(lA0, lA1), __hadd2(lA2v, lA3));
    const __half2 cB2 = __hadd2(__hadd2(lB0, lB1), __hadd2(lB2v, lB3));
    unsigned ccf = __byte_perm(h2u(__hadd2(cA2, magic)), h2u(__hadd2(cB2, magic)), 0x6420);

    ccf = __reduce_add_sync(0xffffffffu, ccf);
    sP  = __reduce_add_sync(0xffffffffu, sP);
    sQ  = __reduce_add_sync(0xffffffffu, sQ);

    const int cAP = (int)(ccf & 255u);
    const int cAQ = (int)((ccf >> 8) & 255u);
    const int cBP = (int)((ccf >> 16) & 255u);
    const int cBQ = (int)(ccf >> 24);

    const int TAP = (int)(A2 & 0xFFFFu) + MIDOFF, TAQ = (int)(A2 >> 16) + MIDOFF;
    const int TBP = (int)(B2 & 0xFFFFu) + MIDOFF, TBQ = (int)(B2 >> 16) + MIDOFF;

    const int keptP = (int)sP - KBIAS * (cBP - cAP)
                    + (94 - cBP) * (TBP - KBIAS) - (31 - cAP) * (TAP - KBIAS);
    const int keptQ = (int)sQ - KBIAS * (cBQ - cAQ)
                    + (94 - cBQ) * (TBQ - KBIAS) - (31 - cAQ) * (TAQ - KBIAS);

    scP = __fdividef(63.0f * KSCALE, (float)keptP);
    scQ = __fdividef(63.0f * KSCALE, (float)keptQ);
}

__global__ __launch_bounds__(256, 5)
void tmcfar_kernel(const float* __restrict__ in, float* __restrict__ out,
                   int H, int W)
{
    __shared__ unsigned pairs[TILE_ROWS * PAIR_W];            // 3072 B (build only)
    __shared__ unsigned long long qtile[TILE_ROWS * TILE_WQ]; // 6400 B
    __shared__ int      offs[128];                            // qword-unit offsets
    __shared__ unsigned long long slotTbl[192];               // {mask32, idx16} per slot
    __shared__ __align__(16) unsigned hfull[8][128];          // byte p = pixel p count

    const int tid  = threadIdx.x;
    const int lane = tid & 31;
    const int wrp  = tid >> 5;
    const int bz   = blockIdx.z;
    const int py0  = blockIdx.y * 8;
    const int px0  = blockIdx.x * 32;

    // compacted (dy,dx) offsets of the 126 reference cells (qword units)
    if (tid < 135) {
        int r = tid / 15, c = tid - r * 15;
        bool guard = (r >= 3 && r <= 5 && c >= 6 && c <= 8);
        if (!guard) {
            int rowsBefore = min(max(r - 3, 0), 3);
            int sameRow    = (r >= 3 && r <= 5) ? min(max(c - 6, 0), 3) : 0;
            int gb = 3 * rowsBefore + sameRow;
            offs[tid - gb] = (r - 4) * TILE_WQ + (c - 7);
        }
    }

    // slot table: cell n = (tid&31) + 32*(tid>>5); net mask = window - guard
    if (tid < 192) {
        unsigned long long e = 0;
        const int n = (tid & 31) + 32 * (tid >> 5);
        if (n < 162) {
            const int r = n / 18, u = n - r * 18;
            unsigned m = 0;
            if (u <= 14)            m |= 0x01u;        // P window cols [0,14]
            if (u >= 1 && u <= 15)  m |= 0x100u;       // Q
            if (u >= 2 && u <= 16)  m |= 0x10000u;     // R
            if (u >= 3)             m |= 0x1000000u;   // S (u<=17 always)
            if (r >= 3 && r <= 5) {                    // guard rows
                if (u >= 6 && u <= 8)   m &= ~0x01u;       // P guard cols
                if (u >= 7 && u <= 9)   m &= ~0x100u;
                if (u >= 8 && u <= 10)  m &= ~0x10000u;
                if (u >= 9 && u <= 11)  m &= ~0x1000000u;
            }
            const unsigned idx = (unsigned)((r * TILE_WQ + u) * 4);  // u16 units, warp-relative
            e = ((unsigned long long)m << 32) | idx;
        }
        slotTbl[tid] = e;
    }

    // ---- phase 1: pair tile, entry c = key[c] | key[c+1]<<16 (all 48 cols) ----
    const int gy0 = py0 - 4, gx0 = px0 - 7;
    const float* inb = in + (size_t)bz * H * W;
    for (int idx = tid; idx < TILE_ROWS * PAIR_W; idx += 256) {
        int r = idx / PAIR_W, c = idx - r * PAIR_W;
        int gy = gy0 + r, gx = gx0 + c;
        bool okr = (gy >= 0 && gy < H);
        float v0 = (okr && gx >= 0     && gx < W)     ? inb[gy * W + gx]     : 0.0f;
        float v1 = (okr && gx + 1 >= 0 && gx + 1 < W) ? inb[gy * W + gx + 1] : 0.0f;
        unsigned k0 = min((unsigned)(v0 * KSCALE), 30719u) + (unsigned)KBIAS;
        unsigned k1 = min((unsigned)(v1 * KSCALE), 30719u) + (unsigned)KBIAS;
        pairs[r * PAIR_W + c] = k0 | (k1 << 16);
    }
    __syncthreads();

    // ---- phase 2: qword tile, entry c = k[c..c+3] (c in 0..45) ----
    for (int idx = tid; idx < TILE_ROWS * 46; idx += 256) {
        int r = idx / 46, c = idx - r * 46;
        qtile[r * TILE_WQ + c] =
            (unsigned long long)pairs[r * PAIR_W + c]
          | ((unsigned long long)pairs[r * PAIR_W + c + 2] << 32);
    }
    __syncthreads();

    const int py = py0 + wrp;
    const float centerf = inb[py * W + px0 + lane];
    const bool exY = (py < 4) | (py >= H - 4);   // warp-uniform

    const int o0 = offs[lane];
    const int o1 = offs[lane + 32];
    const int o2 = offs[lane + 64];
    const int o3 = (lane < 30) ? offs[lane + 96] : 0;
    const bool has3 = (lane < 30);

    const unsigned short* qsW = (const unsigned short*)qtile + wrp * TILE_WQ * 4;
    const unsigned long long* qrow = &qtile[(wrp + 4) * TILE_WQ + 7];
    unsigned* hf = &hfull[wrp][0];
    float myscale = 0.0f;

    #pragma unroll 1
    for (int i = 0; i < 8; ++i) {
        // ---- epilogue gather keys: one LDS.64 per reference cell ----
        const unsigned long long* p = qrow + 4 * i;
        const unsigned long long w0 = p[o0];
        const unsigned long long w1 = p[o1];
        const unsigned long long w2 = p[o2];
        const unsigned long long w3 = p[o3];
        const unsigned a0 = (unsigned)w0, b0 = (unsigned)(w0 >> 32);
        const unsigned a1 = (unsigned)w1, b1 = (unsigned)(w1 >> 32);
        const unsigned a2 = (unsigned)w2, b2 = (unsigned)(w2 >> 32);
        const unsigned a3 = has3 ? (unsigned)w3 : SENT2;
        const unsigned b3 = has3 ? (unsigned)(w3 >> 32) : SENT2;

        // ---- shared-window histogram: 6 atomics max per lane, net masks ----
        *reinterpret_cast<uint4*>(&hf[lane * 4]) = make_uint4(0u, 0u, 0u, 0u);
        __syncwarp();
        const int sh = 16 * i;   // window slides 4 cols/quad = 16 u16
        #pragma unroll
        for (int j = 0; j < 5; ++j) {
            const unsigned long long e = slotTbl[j * 32 + lane];
            const unsigned k = qsW[(unsigned)(e & 0xFFFFu) + sh];
            atomicAdd(&hf[k >> 8], (unsigned)(e >> 32));
        }
        if (lane < 2) {
            const unsigned long long e = slotTbl[160 + lane];
            const unsigned k = qsW[(unsigned)(e & 0xFFFFu) + sh];
            atomicAdd(&hf[k >> 8], (unsigned)(e >> 32));
        }
        __syncwarp();

        // ---- lane-serial byte-SIMD prefix + ONE packed warp scan (bytes <= 128) ----
        const uint4 cf = *reinterpret_cast<const uint4*>(&hf[lane * 4]);
        unsigned q0 = cf.x;
        unsigned q1 = q0 + cf.y;
        unsigned q2 = q1 + cf.z;
        unsigned q3 = q2 + cf.w;
        unsigned incl = q3;
        #pragma unroll
        for (int d = 1; d < 32; d <<= 1) {
            unsigned t = __shfl_up_sync(0xffffffffu, incl, d);
            if (lane >= d) incl += t;
        }
        const unsigned excl = incl - q3;
        q0 += excl; q1 += excl; q2 += excl; q3 += excl;

        // ---- byte-SIMD bucket search for all 4 pixels, TWO REDUX total ----
        const unsigned g30 = (((0x9E9E9E9Eu - q0) >> 7) & 0x01010101u)
                           + (((0x9E9E9E9Eu - q1) >> 7) & 0x01010101u)
                           + (((0x9E9E9E9Eu - q2) >> 7) & 0x01010101u)
                           + (((0x9E9E9E9Eu - q3) >> 7) & 0x01010101u);
        const unsigned g94 = (((0xDEDEDEDEu - q0) >> 7) & 0x01010101u)
                           + (((0xDEDEDEDEu - q1) >> 7) & 0x01010101u)
                           + (((0xDEDEDEDEu - q2) >> 7) & 0x01010101u)
                           + (((0xDEDEDEDEu - q3) >> 7) & 0x01010101u);
        const unsigned w30 = __reduce_add_sync(0xffffffffu, g30);  // bytes (bAP,bAQ,bAR,bAS)
        const unsigned w94 = __reduce_add_sync(0xffffffffu, g94);  // bytes (bBP,bBQ,bBR,bBS)

        // bucket base = bin<<8: bytes to halfword-high positions per pair
        const unsigned A2pq = __byte_perm(w30, 0, 0x1404);   // (0,bAP,0,bAQ)
        const unsigned B2pq = __byte_perm(w94, 0, 0x1404);
        const unsigned A2rs = __byte_perm(w30, 0, 0x3424);   // (0,bAR,0,bAS)
        const unsigned B2rs = __byte_perm(w94, 0, 0x3424);

        float s0, s1, s2, s3;
        const int pxP = px0 + 4 * i;
        if (exY | (pxP < 7) | (pxP + 3 >= W - 7)) {
            // window touches zero padding: 8 exact bisection steps inside bucket
            bisect_pair<7, 0>(a0, a1, a2, a3, A2pq, B2pq, s0, s1);
            bisect_pair<7, 0>(b0, b1, b2, b3, A2rs, B2rs, s2, s3);
        } else {
            // clean: 256-wide bucket direct, midpoint +-128 substitution
            bisect_pair<7, 8>(a0, a1, a2, a3, A2pq, B2pq, s0, s1);
            bisect_pair<7, 8>(b0, b1, b2, b3, A2rs, B2rs, s2, s3);
        }
        if (lane == 4 * i)     myscale = s0;
        if (lane == 4 * i + 1) myscale = s1;
        if (lane == 4 * i + 2) myscale = s2;
        if (lane == 4 * i + 3) myscale = s3;
    }

    out[(size_t)bz * H * W + py * W + px0 + lane] = centerf * myscale;
}

extern "C" void kernel_launch(void* const* d_in, const int* in_sizes, int n_in,
                              void* d_out, int out_size)
{
    const float* in = (const float*)d_in[0];
    float* out = (float*)d_out;
    const int H = 512, W = 512;
    const int B = in_sizes[0] / (H * W);

    dim3 grid(W / 32, H / 8, B);
    dim3 block(256);
    tmcfar_kernel<<<grid, block>>>(in, out, H, W);
}

// round 16
// speedup vs baseline: 1.0650x; 1.0057x over previous
#include <cuda_runtime.h>
#include <cuda_fp16.h>
#include <cstdint>

// TM-CFAR: out = rd_map / trimmed_mean(sorted 126 reference cells, ranks [31,94))
// Window 9x15, guard 3x3, zero padding.
//
// Round-16: round-15 (64x8 patch, 2 px/thread) with the phase-2 coverage fix:
// qword tile must be built through c=77 (histogram reads k[u+4i], u<=17, i<=15);
// the c<=74 guard left qwords 75..77 uninitialized -> corrupted buckets for the
// last quad of each row.
//  - single shared-window histogram, guard-folded net byte-masks (exact counts)
//  - slot table u64 {mask32, idx16} x 192 in smem
//  - clean quads: 256-wide bucket direct (midpoint +-128); padding-affected
//    quads: 8 exact bisection steps inside bucket

#define TILE_WQ   80      // qword tile stride (u64 units) == pair stride
#define TILE_ROWS 16
#define KBIAS     1024
#define KSCALE    30720.0f
#define SENT2     0x7BFF7BFFu   // max-finite fp16: never below any threshold, hmul-safe

static __device__ __forceinline__ unsigned h2u(__half2 h) { return *reinterpret_cast<unsigned*>(&h); }
static __device__ __forceinline__ __half2  u2h(unsigned u) { return *reinterpret_cast<__half2*>(&u); }

// STARTBIT < STOPBIT => zero bisection steps, epilogue only, MIDOFF = 1<<(STOPBIT-1)
template <int STARTBIT, int STOPBIT>
static __device__ __forceinline__ void bisect_pair(
    unsigned pk0, unsigned pk1, unsigned pk2, unsigned pk3,
    unsigned A2, unsigned B2,
    float& scP, float& scQ)
{
    const __half2 magic = u2h(0x64006400u);   // (1024.0, 1024.0)

    #pragma unroll
    for (int bit = STARTBIT; bit >= STOPBIT; --bit) {
        const unsigned step2 = (1u << bit) * 0x10001u;
        const __half2 mA = u2h(A2 + step2);
        const __half2 mB = u2h(B2 + step2);

        __half2 sA = __hadd2(__hadd2(__hlt2(u2h(pk0), mA), __hlt2(u2h(pk1), mA)),
                             __hadd2(__hlt2(u2h(pk2), mA), __hlt2(u2h(pk3), mA)));
        __half2 sB = __hadd2(__hadd2(__hlt2(u2h(pk0), mB), __hlt2(u2h(pk1), mB)),
                             __hadd2(__hlt2(u2h(pk2), mB), __hlt2(u2h(pk3), mB)));
        const unsigned Ar = h2u(__hadd2(sA, magic));   // bytes (cAP, 0x64, cAQ, 0x64)
        const unsigned Br = h2u(__hadd2(sB, magic));
        unsigned cc = __byte_perm(Ar, Br, 0x6420);     // (cAP, cAQ, cBP, cBQ)
        cc = __reduce_add_sync(0xffffffffu, cc);

        // byte-wise accept flags: bytes 0,1 vs 30 ; bytes 2,3 vs 94
        const unsigned f = ((0xDEDE9E9Eu - cc) >> 7) & 0x01010101u;
        A2 += __byte_perm(f, 0, 0x4140) << bit;   // (fAP | fAQ<<16) << bit
        B2 += __byte_perm(f, 0, 0x4342) << bit;
    }

    const int MIDOFF = (STOPBIT > 0) ? (1 << (STOPBIT - 1)) : 0;

    // ---- epilogue: exact counts below brackets + masked range sums ----
    const __half2 hA = u2h(A2), hB = u2h(B2);
    const __half2 lA0 = __hlt2(u2h(pk0), hA), lA1 = __hlt2(u2h(pk1), hA);
    const __half2 lA2v = __hlt2(u2h(pk2), hA), lA3 = __hlt2(u2h(pk3), hA);
    const __half2 lB0 = __hlt2(u2h(pk0), hB), lB1 = __hlt2(u2h(pk1), hB);
    const __half2 lB2v = __hlt2(u2h(pk2), hB), lB3 = __hlt2(u2h(pk3), hB);

    const unsigned in0 = h2u(lB0) & ~h2u(lA0);
    const unsigned in1 = h2u(lB1) & ~h2u(lA1);
    const unsigned in2 = h2u(lB2v) & ~h2u(lA2v);
    const unsigned in3 = h2u(lB3) & ~h2u(lA3);

    const unsigned km0 = h2u(__hmul2(u2h(pk0), u2h(in0)));
    const unsigned km1 = h2u(__hmul2(u2h(pk1), u2h(in1)));
    const unsigned km2 = h2u(__hmul2(u2h(pk2), u2h(in2)));
    const unsigned km3 = h2u(__hmul2(u2h(pk3), u2h(in3)));

    // halfword-pair pack + SIMD add (lanes <= 2*31743, no carry)
    const unsigned lo01 = __byte_perm(km0, km1, 0x5410);
    const unsigned lo23 = __byte_perm(km2, km3, 0x5410);
    const unsigned hi01 = __byte_perm(km0, km1, 0x7632);
    const unsigned hi23 = __byte_perm(km2, km3, 0x7632);
    const unsigned vlo = __vadd2(lo01, lo23);
    const unsigned vhi = __vadd2(hi01, hi23);
    unsigned sP = (vlo & 0xFFFFu) + (vlo >> 16);
    unsigned sQ = (vhi & 0xFFFFu) + (vhi >> 16);

    const __half2 cA2 = __hadd2(__hadd2(lA0, lA1), __hadd2(lA2v, lA3));
    const __half2 cB2 = __hadd2(__hadd2(lB0, lB1), __hadd2(lB2v, lB3));
    unsigned ccf = __byte_perm(h2u(__hadd2(cA2, magic)), h2u(__hadd2(cB2, magic)), 0x6420);

    ccf = __reduce_add_sync(0xffffffffu, ccf);
    sP  = __reduce_add_sync(0xffffffffu, sP);
    sQ  = __reduce_add_sync(0xffffffffu, sQ);

    const int cAP = (int)(ccf & 255u);
    const int cAQ = (int)((ccf >> 8) & 255u);
    const int cBP = (int)((ccf >> 16) & 255u);
    const int cBQ = (int)(ccf >> 24);

    const int TAP = (int)(A2 & 0xFFFFu) + MIDOFF, TAQ = (int)(A2 >> 16) + MIDOFF;
    const int TBP = (int)(B2 & 0xFFFFu) + MIDOFF, TBQ = (int)(B2 >> 16) + MIDOFF;

    const int keptP = (int)sP - KBIAS * (cBP - cAP)
                    + (94 - cBP) * (TBP - KBIAS) - (31 - cAP) * (TAP - KBIAS);
    const int keptQ = (int)sQ - KBIAS * (cBQ - cAQ)
                    + (94 - cBQ) * (TBQ - KBIAS) - (31 - cAQ) * (TAQ - KBIAS);

    scP = __fdividef(63.0f * KSCALE, (float)keptP);
    scQ = __fdividef(63.0f * KSCALE, (float)keptQ);
}

__global__ __launch_bounds__(256, 5)
void tmcfar_kernel(const float* __restrict__ in, float* __restrict__ out,
                   int H, int W)
{
    __shared__ unsigned pairs[TILE_ROWS * TILE_WQ];           // 5120 B (build only)
    __shared__ unsigned long long qtile[TILE_ROWS * TILE_WQ]; // 10240 B
    __shared__ int      offs[128];                            // qword-unit offsets
    __shared__ unsigned long long slotTbl[192];               // {mask32, idx16} per slot
    __shared__ __align__(16) unsigned hfull[8][128];          // byte p = pixel p count

    const int tid  = threadIdx.x;
    const int lane = tid & 31;
    const int wrp  = tid >> 5;
    const int bz   = blockIdx.z;
    const int py0  = blockIdx.y * 8;
    const int px0  = blockIdx.x * 64;

    // compacted (dy,dx) offsets of the 126 reference cells (qword units)
    if (tid < 135) {
        int r = tid / 15, c = tid - r * 15;
        bool guard = (r >= 3 && r <= 5 && c >= 6 && c <= 8);
        if (!guard) {
            int rowsBefore = min(max(r - 3, 0), 3);
            int sameRow    = (r >= 3 && r <= 5) ? min(max(c - 6, 0), 3) : 0;
            int gb = 3 * rowsBefore + sameRow;
            offs[tid - gb] = (r - 4) * TILE_WQ + (c - 7);
        }
    }

    // slot table: cell n = (tid&31) + 32*(tid>>5); net mask = window - guard
    if (tid < 192) {
        unsigned long long e = 0;
        const int n = (tid & 31) + 32 * (tid >> 5);
        if (n < 162) {
            const int r = n / 18, u = n - r * 18;
            unsigned m = 0;
            if (u <= 14)            m |= 0x01u;        // P window cols [0,14]
            if (u >= 1 && u <= 15)  m |= 0x100u;       // Q
            if (u >= 2 && u <= 16)  m |= 0x10000u;     // R
            if (u >= 3)             m |= 0x1000000u;   // S (u<=17 always)
            if (r >= 3 && r <= 5) {                    // guard rows
                if (u >= 6 && u <= 8)   m &= ~0x01u;       // P guard cols
                if (u >= 7 && u <= 9)   m &= ~0x100u;
                if (u >= 8 && u <= 10)  m &= ~0x10000u;
                if (u >= 9 && u <= 11)  m &= ~0x1000000u;
            }
            const unsigned idx = (unsigned)((r * TILE_WQ + u) * 4);  // u16 units, warp-relative
            e = ((unsigned long long)m << 32) | idx;
        }
        slotTbl[tid] = e;
    }

    // ---- phase 1: pair tile (2D mapping, no division) ----
    // 16 rows x 80 cols of pair entries; thread (trow, tcol) handles 5 cols.
    const int gy0 = py0 - 4, gx0 = px0 - 7;
    const float* inb = in + (size_t)bz * H * W;
    {
        const int trow = tid >> 4;      // 0..15
        const int tcol = tid & 15;      // 0..15
        const int gy = gy0 + trow;
        const bool okr = (gy >= 0) & (gy < H);
        const float* rowp = inb + gy * W;
        #pragma unroll
        for (int k = 0; k < 5; ++k) {
            const int c = tcol + 16 * k;
            const int gx = gx0 + c;
            float v0 = (okr && gx >= 0     && gx < W)     ? rowp[gx]     : 0.0f;
            float v1 = (okr && gx + 1 >= 0 && gx + 1 < W) ? rowp[gx + 1] : 0.0f;
            unsigned k0 = min((unsigned)(v0 * KSCALE), 30719u) + (unsigned)KBIAS;
            unsigned k1 = min((unsigned)(v1 * KSCALE), 30719u) + (unsigned)KBIAS;
            pairs[trow * TILE_WQ + c] = k0 | (k1 << 16);
        }
    }
    __syncthreads();

    // ---- phase 2: qword tile, entry c = k[c..c+3] ----
    // FIX vs round 15: histogram reads k[u+4i] up to c=77 (u<=17, i<=15), so
    // build through c<=77 (pairs[c+2] exists through c+2=79).
    {
        const int trow = tid >> 4;
        const int tcol = tid & 15;
        #pragma unroll
        for (int k = 0; k < 5; ++k) {
            const int c = tcol + 16 * k;
            if (c <= 77) {
                qtile[trow * TILE_WQ + c] =
                    (unsigned long long)pairs[trow * TILE_WQ + c]
                  | ((unsigned long long)pairs[trow * TILE_WQ + c + 2] << 32);
            }
        }
    }
    __syncthreads();

    const int py = py0 + wrp;
    const bool exY = (py < 4) | (py >= H - 4);   // warp-uniform

    const int o0 = offs[lane];
    const int o1 = offs[lane + 32];
    const int o2 = offs[lane + 64];
    const int o3 = (lane < 30) ? offs[lane + 96] : 0;
    const bool has3 = (lane < 30);

    const unsigned short* qsW = (const unsigned short*)qtile + wrp * TILE_WQ * 4;
    const unsigned long long* qrow = &qtile[(wrp + 4) * TILE_WQ + 7];
    unsigned* hf = &hfull[wrp][0];
    float ms0 = 0.0f, ms1 = 0.0f;   // pixels (px0+lane) and (px0+lane+32)

    #pragma unroll 1
    for (int i = 0; i < 16; ++i) {
        // ---- epilogue gather keys: one LDS.64 per reference cell ----
        const unsigned long long* p = qrow + 4 * i;
        const unsigned long long w0 = p[o0];
        const unsigned long long w1 = p[o1];
        const unsigned long long w2 = p[o2];
        const unsigned long long w3 = p[o3];
        const unsigned a0 = (unsigned)w0, b0 = (unsigned)(w0 >> 32);
        const unsigned a1 = (unsigned)w1, b1 = (unsigned)(w1 >> 32);
        const unsigned a2 = (unsigned)w2, b2 = (unsigned)(w2 >> 32);
        const unsigned a3 = has3 ? (unsigned)w3 : SENT2;
        const unsigned b3 = has3 ? (unsigned)(w3 >> 32) : SENT2;

        // ---- shared-window histogram: 6 atomics max per lane, net masks ----
        *reinterpret_cast<uint4*>(&hf[lane * 4]) = make_uint4(0u, 0u, 0u, 0u);
        __syncwarp();
        const int sh = 16 * i;   // window slides 4 cols/quad = 16 u16
        #pragma unroll
        for (int j = 0; j < 5; ++j) {
            const unsigned long long e = slotTbl[j * 32 + lane];
            const unsigned k = qsW[(unsigned)(e & 0xFFFFu) + sh];
            atomicAdd(&hf[k >> 8], (unsigned)(e >> 32));
        }
        if (lane < 2) {
            const unsigned long long e = slotTbl[160 + lane];
            const unsigned k = qsW[(unsigned)(e & 0xFFFFu) + sh];
            atomicAdd(&hf[k >> 8], (unsigned)(e >> 32));
        }
        __syncwarp();

        // ---- lane-serial byte-SIMD prefix + ONE packed warp scan (bytes <= 128) ----
        const uint4 cf = *reinterpret_cast<const uint4*>(&hf[lane * 4]);
        unsigned q0 = cf.x;
        unsigned q1 = q0 + cf.y;
        unsigned q2 = q1 + cf.z;
        unsigned q3 = q2 + cf.w;
        unsigned incl = q3;
        #pragma unroll
        for (int d = 1; d < 32; d <<= 1) {
            unsigned t = __shfl_up_sync(0xffffffffu, incl, d);
            if (lane >= d) incl += t;
        }
        const unsigned excl = incl - q3;
        q0 += excl; q1 += excl; q2 += excl; q3 += excl;

        // ---- byte-SIMD bucket search for all 4 pixels, TWO REDUX total ----
        const unsigned g30 = (((0x9E9E9E9Eu - q0) >> 7) & 0x01010101u)
                           + (((0x9E9E9E9Eu - q1) >> 7) & 0x01010101u)
                           + (((0x9E9E9E9Eu - q2) >> 7) & 0x01010101u)
                           + (((0x9E9E9E9Eu - q3) >> 7) & 0x01010101u);
        const unsigned g94 = (((0xDEDEDEDEu - q0) >> 7) & 0x01010101u)
                           + (((0xDEDEDEDEu - q1) >> 7) & 0x01010101u)
                           + (((0xDEDEDEDEu - q2) >> 7) & 0x01010101u)
                           + (((0xDEDEDEDEu - q3) >> 7) & 0x01010101u);
        const unsigned w30 = __reduce_add_sync(0xffffffffu, g30);  // bytes (bAP,bAQ,bAR,bAS)
        const unsigned w94 = __reduce_add_sync(0xffffffffu, g94);  // bytes (bBP,bBQ,bBR,bBS)

        // bucket base = bin<<8: bytes to halfword-high positions per pair
        const unsigned A2pq = __byte_perm(w30, 0, 0x1404);   // (0,bAP,0,bAQ)
        const unsigned B2pq = __byte_perm(w94, 0, 0x1404);
        const unsigned A2rs = __byte_perm(w30, 0, 0x3424);   // (0,bAR,0,bAS)
        const unsigned B2rs = __byte_perm(w94, 0, 0x3424);

        float s0, s1, s2, s3;
        const int pxP = px0 + 4 * i;
        if (exY | (pxP < 7) | (pxP + 3 >= W - 7)) {
            // window touches zero padding: 8 exact bisection steps inside bucket
            bisect_pair<7, 0>(a0, a1, a2, a3, A2pq, B2pq, s0, s1);
            bisect_pair<7, 0>(b0, b1, b2, b3, A2rs, B2rs, s2, s3);
        } else {
            // clean: 256-wide bucket direct, midpoint +-128 substitution
            bisect_pair<7, 8>(a0, a1, a2, a3, A2pq, B2pq, s0, s1);
            bisect_pair<7, 8>(b0, b1, b2, b3, A2rs, B2rs, s2, s3);
        }
        // quad i covers local pixels 4i..4i+3; lanes store px lane and lane+32
        if (i < 8) {
            if (lane == 4 * i)     ms0 = s0;
            if (lane == 4 * i + 1) ms0 = s1;
            if (lane == 4 * i + 2) ms0 = s2;
            if (lane == 4 * i + 3) ms0 = s3;
        } else {
            const int t = 4 * i - 32;
            if (lane == t)     ms1 = s0;
            if (lane == t + 1) ms1 = s1;
            if (lane == t + 2) ms1 = s2;
            if (lane == t + 3) ms1 = s3;
        }
    }

    const size_t rowbase = (size_t)bz * H * W + (size_t)py * W + px0;
    out[rowbase + lane]      = inb[py * W + px0 + lane]      * ms0;
    out[rowbase + lane + 32] = inb[py * W + px0 + lane + 32] * ms1;
}

extern "C" void kernel_launch(void* const* d_in, const int* in_sizes, int n_in,
                              void* d_out, int out_size)
{
    const float* in = (const float*)d_in[0];
    float* out = (float*)d_out;
    const int H = 512, W = 512;
    const int B = in_sizes[0] / (H * W);

    dim3 grid(W / 64, H / 8, B);
    dim3 block(256);
    tmcfar_kernel<<<grid, block>>>(in, out, H, W);
}